// round 5
// baseline (speedup 1.0000x reference)
#include <cuda_runtime.h>

// ---------------- problem constants ----------------
#define S_LEN  512
#define DIN    5
#define HID    128
#define GATES  512
#define NBLK   128     // recurrence blocks, each owns BPB batch rows
#define BPB    8
#define NG     32      // k-groups (of 4) per 128-wide K
#define NCACHE 23      // k-groups cached in smem
#define NTH    384     // phase kernel threads = 128 j x 3 kh

// phase smem layout (float offsets)
#define OFF_WC  0
#define OFF_HH  (NCACHE*GATES*4)          // 47104 : 2 x [8][128] h double buffer
#define OFF_XA  (OFF_HH + 2*BPB*HID)      // 49152 : 2 slots x [8b][4q][128j]
#define OFF_XS  (OFF_XA + 2*4096)         // 57344 : 2 x [8][8] staged x
#define PH_SMEM_BYTES ((OFF_XS + 128)*4)  // 229888 (< 232448 limit)

// gemm smem
#define G_NCOL   128
#define G_OFF_WS 0                        // 32 g x 128 c x 4 floats = 16384 floats
#define G_OFF_HS (NG*G_NCOL*4)
#define G_SMEM_BYTES ((G_OFF_HS + 2*1024)*4)   // 73728 -> 2 blocks/SM

// ---------------- global scratch (static) ----------------
__device__ __align__(16) float g_P1[NG * GATES * 4];   // packed w_hh0
__device__ __align__(16) float g_P2[NG * GATES * 4];   // packed w_hh1
__device__ __align__(16) float g_P3[NG * GATES * 4];   // packed w_ih1
__device__ __align__(16) float g_h1 [(size_t)NBLK * S_LEN * BPB * HID];    // [blk][t][b][j]
__device__ __align__(16) float g_xg1[(size_t)NBLK * S_LEN * GATES * BPB];  // [blk][t][col][b]

// ---------------- helpers ----------------
typedef unsigned long long u64;
__device__ __forceinline__ void ffma2(u64 &d, u64 a, u64 b) {
    asm("fma.rn.f32x2 %0, %1, %2, %0;" : "+l"(d) : "l"(a), "l"(b));
}
__device__ __forceinline__ float flo(u64 v) { return __uint_as_float((unsigned)v); }
__device__ __forceinline__ float fhi(u64 v) { return __uint_as_float((unsigned)(v >> 32)); }
__device__ __forceinline__ float sigf(float x) {
    return __fdividef(1.0f, 1.0f + __expf(-x));
}
__device__ __forceinline__ float tanhf_fast(float x) {
    float e = __expf(2.0f * x);
    return 1.0f - __fdividef(2.0f, e + 1.0f);
}

// cached-group accumulation: 4 cols (q*128+j) x 8 b
template<int G0, int G1>
__device__ __forceinline__ void accum_range(u64 (&acc)[4][8],
                                            const ulonglong2* __restrict__ W,
                                            const ulonglong2* __restrict__ H,
                                            int j) {
#pragma unroll 2
    for (int g = G0; g < G1; g++) {
        ulonglong2 w[4];
#pragma unroll
        for (int q = 0; q < 4; q++) w[q] = W[g * GATES + q * HID + j];
#pragma unroll
        for (int b = 0; b < 8; b++) {
            ulonglong2 hv = H[b * 32 + g];
#pragma unroll
            for (int q = 0; q < 4; q++) {
                ffma2(acc[q][b], w[q].x, hv.x);
                ffma2(acc[q][b], w[q].y, hv.y);
            }
        }
    }
}

// ---------------- K1: pack weights ----------------
__global__ void pack_kernel(const float* __restrict__ whh0,
                            const float* __restrict__ whh1,
                            const float* __restrict__ wih1) {
    int i = blockIdx.x * blockDim.x + threadIdx.x;
    if (i >= GATES * HID) return;
    int col = i / HID, k = i % HID;
    int g = k >> 2, dk = k & 3;
    size_t o = ((size_t)g * GATES + col) * 4 + dk;
    g_P1[o] = whh0[col * HID + k];
    g_P2[o] = whh1[col * HID + k];
    g_P3[o] = wih1[col * HID + k];
}

// ---------------- K3: xg1 = h1 @ w_ih1^T + biases ----------------
// grid (4 colquads, NBLK, 2 t-halves), 256 thr, 2 blocks/SM.
// thread: cq = tid>>2 -> 2 cols; bh = tid&3 -> 2 batch rows.
__global__ void __launch_bounds__(256, 2) xg1_gemm(const float* __restrict__ bih1,
                                                   const float* __restrict__ bhh1) {
    extern __shared__ float sm[];
    const int tid = threadIdx.x;
    const int cqr = blockIdx.x, blk = blockIdx.y;
    const int t0  = blockIdx.z * (S_LEN / 2);
    const int cq  = tid >> 2;            // 0..63
    const int bh  = tid & 3;             // b = 2bh, 2bh+1
    const int c0  = cqr * G_NCOL + cq * 2;

    // weight slice: 32 g x 128 cols
    {
        const float4* src = (const float4*)g_P3;
        float4*       dst = (float4*)(sm + G_OFF_WS);
        for (int i = tid; i < NG * G_NCOL; i += 256) {
            int g = i >> 7, c = i & 127;
            dst[i] = __ldg(&src[g * GATES + cqr * G_NCOL + c]);
        }
    }
    const float bs0 = __ldg(bih1 + c0)     + __ldg(bhh1 + c0);
    const float bs1 = __ldg(bih1 + c0 + 1) + __ldg(bhh1 + c0 + 1);

    ((float4*)(sm + G_OFF_HS))[tid] =
        __ldg((const float4*)(g_h1 + ((size_t)blk * S_LEN + t0) * (BPB * HID)) + tid);
    __syncthreads();

    const ulonglong2* WsD = (const ulonglong2*)(sm + G_OFF_WS);
    int pb = 0;
    for (int tt = 0; tt < S_LEN / 2; tt++) {
        int t = t0 + tt;
        bool has = (tt + 1 < S_LEN / 2);
        float4 pre;
        if (has)
            pre = __ldg((const float4*)(g_h1 + ((size_t)blk * S_LEN + t + 1) * (BPB * HID)) + tid);

        const ulonglong2* HtD = (const ulonglong2*)(sm + G_OFF_HS + pb * 1024);
        u64 acc[2][2] = {{0ull,0ull},{0ull,0ull}};
#pragma unroll 4
        for (int g = 0; g < NG; g++) {
            ulonglong2 w0 = WsD[g * G_NCOL + cq * 2];
            ulonglong2 w1 = WsD[g * G_NCOL + cq * 2 + 1];
#pragma unroll
            for (int r = 0; r < 2; r++) {
                ulonglong2 hv = HtD[(bh * 2 + r) * 32 + g];
                ffma2(acc[0][r], w0.x, hv.x); ffma2(acc[0][r], w0.y, hv.y);
                ffma2(acc[1][r], w1.x, hv.x); ffma2(acc[1][r], w1.y, hv.y);
            }
        }
        float2 o0 = make_float2(flo(acc[0][0]) + fhi(acc[0][0]) + bs0,
                                flo(acc[0][1]) + fhi(acc[0][1]) + bs0);
        float2 o1 = make_float2(flo(acc[1][0]) + fhi(acc[1][0]) + bs1,
                                flo(acc[1][1]) + fhi(acc[1][1]) + bs1);
        size_t base = (size_t)(blk * S_LEN + t) * (GATES * BPB);
        *(float2*)(g_xg1 + base + (size_t)c0 * BPB + bh * 2)       = o0;
        *(float2*)(g_xg1 + base + (size_t)(c0 + 1) * BPB + bh * 2) = o1;

        if (has) ((float4*)(sm + G_OFF_HS + (pb ^ 1) * 1024))[tid] = pre;
        __syncthreads();
        pb ^= 1;
    }
}

// ---------------- K2/K4: recurrent phases (K=128) ----------------
// 384 threads = 128 j x 3 kh. Thread owns all 4 gate-cols of j, 8 batch rows,
// over its K third. kh0: g0-9 + finalize b0-3. kh1: g10-19 + finalize b4-7.
// kh2: g20-22 cached + g23-31 L2-streamed; phase1 x staging; no finalize.
template<int PHASE>
__global__ void __launch_bounds__(NTH, 1) lstm_phase(
    const float* __restrict__ x,
    const float* __restrict__ wih0,
    const float* __restrict__ bih,
    const float* __restrict__ bhh,
    const float* __restrict__ fcw,
    const float* __restrict__ fcb,
    float* __restrict__ out)
{
    extern __shared__ float sm[];
    const float* Pg = (PHASE == 1) ? g_P1 : g_P2;

    const int tid = threadIdx.x;
    const int j   = tid & (HID - 1);
    const int kh  = tid >> 7;            // 0,1,2
    const int blk = blockIdx.x;
    const int bg0 = blk * BPB;

    // finalizer constants (phase1 input path)
    float bias[4], wihr[4][DIN];
    if (PHASE == 1 && kh < 2) {
#pragma unroll
        for (int q = 0; q < 4; q++) {
            int r = q * HID + j;
            bias[q] = __ldg(bih + r) + __ldg(bhh + r);
#pragma unroll
            for (int d = 0; d < DIN; d++) wihr[q][d] = __ldg(wih0 + r * DIN + d);
        }
    }

    // load cached weights; zero h buffers; stage x(t=0)
    {
        const float4* src = (const float4*)Pg;
        float4*       dst = (float4*)(sm + OFF_WC);
        for (int i = tid; i < NCACHE * GATES; i += NTH) dst[i] = __ldg(src + i);
    }
    for (int i = tid; i < 2 * BPB * HID; i += NTH) sm[OFF_HH + i] = 0.f;
    if (PHASE == 1 && tid >= 256 && tid < 320) {
        int st = tid - 256, b = st >> 3, d = st & 7;
        if (d < DIN)
            sm[OFF_XS + b * 8 + d] = __ldg(x + ((size_t)(bg0 + b) * S_LEN + 0) * DIN + d);
    }
    __syncthreads();

    const ulonglong2* WcD = (const ulonglong2*)(sm + OFF_WC);
    const ulonglong2* PgD = (const ulonglong2*)Pg;
    float c[4] = {0.f, 0.f, 0.f, 0.f};

    for (int t = 0; t < S_LEN; t++) {
        const int rb = t & 1, wb = rb ^ 1;
        const ulonglong2* HrD = (const ulonglong2*)(sm + OFF_HH + rb * BPB * HID);

        // early independent loads
        float4 xq[4];
        float  xst = 0.f;
        if (PHASE == 2 && kh < 2) {
            const float4* xp = (const float4*)(g_xg1 + (size_t)(blk * S_LEN + t) * (GATES * BPB));
#pragma unroll
            for (int q = 0; q < 4; q++) xq[q] = __ldg(xp + (q * HID + j) * 2 + kh);
        }
        if (PHASE == 1 && kh == 2 && tid < 320) {
            int st = tid - 256, b = st >> 3, d = st & 7;
            int tn = (t + 1 < S_LEN) ? t + 1 : t;
            if (d < DIN) xst = __ldg(x + ((size_t)(bg0 + b) * S_LEN + tn) * DIN + d);
        }

        u64 acc[4][8];
#pragma unroll
        for (int q = 0; q < 4; q++)
#pragma unroll
            for (int b = 0; b < 8; b++) acc[q][b] = 0ull;

        if (kh == 0) {
            accum_range<0, 10>(acc, WcD, HrD, j);
        } else if (kh == 1) {
            accum_range<10, 20>(acc, WcD, HrD, j);
        } else {
            // rolling L2 prefetch for groups 23..31, issued before cached work
            ulonglong2 wp[3][4];
#pragma unroll
            for (int s = 0; s < 3; s++)
#pragma unroll
                for (int q = 0; q < 4; q++)
                    wp[s][q] = __ldg(&PgD[(23 + s) * GATES + q * HID + j]);
            accum_range<20, 23>(acc, WcD, HrD, j);
#pragma unroll
            for (int s = 0; s < 9; s++) {
                int g = 23 + s;
                ulonglong2 w[4];
#pragma unroll
                for (int q = 0; q < 4; q++) w[q] = wp[s % 3][q];
                if (s + 3 < 9) {
#pragma unroll
                    for (int q = 0; q < 4; q++)
                        wp[s % 3][q] = __ldg(&PgD[(g + 3) * GATES + q * HID + j]);
                }
#pragma unroll
                for (int b = 0; b < 8; b++) {
                    ulonglong2 hv = HrD[b * 32 + g];
#pragma unroll
                    for (int q = 0; q < 4; q++) {
                        ffma2(acc[q][b], w[q].x, hv.x);
                        ffma2(acc[q][b], w[q].y, hv.y);
                    }
                }
            }
        }

        // reduce f32x2 lanes, export partials
        float pr[4][8];
#pragma unroll
        for (int q = 0; q < 4; q++)
#pragma unroll
            for (int b = 0; b < 8; b++) pr[q][b] = flo(acc[q][b]) + fhi(acc[q][b]);

        if (kh == 0) {
#pragma unroll
            for (int b = 4; b < 8; b++)
#pragma unroll
                for (int q = 0; q < 4; q++)
                    sm[OFF_XA + (b * 4 + q) * HID + j] = pr[q][b];
        } else if (kh == 1) {
#pragma unroll
            for (int b = 0; b < 4; b++)
#pragma unroll
                for (int q = 0; q < 4; q++)
                    sm[OFF_XA + (b * 4 + q) * HID + j] = pr[q][b];
        } else {
#pragma unroll
            for (int b = 0; b < 8; b++)
#pragma unroll
                for (int q = 0; q < 4; q++)
                    sm[OFF_XA + 4096 + (b * 4 + q) * HID + j] = pr[q][b];
        }
        __syncthreads();   // 1

        if (kh < 2) {
            float* Hw = sm + OFF_HH + wb * BPB * HID;
            const float* xs = sm + OFF_XS + rb * 64;
#pragma unroll
            for (int r = 0; r < 4; r++) {
                int b = kh * 4 + r;
                float gate[4];
#pragma unroll
                for (int q = 0; q < 4; q++)
                    gate[q] = pr[q][b]
                            + sm[OFF_XA + (b * 4 + q) * HID + j]
                            + sm[OFF_XA + 4096 + (b * 4 + q) * HID + j];
                if (PHASE == 1) {
#pragma unroll
                    for (int q = 0; q < 4; q++) {
                        float s = bias[q];
#pragma unroll
                        for (int d = 0; d < DIN; d++) s = fmaf(wihr[q][d], xs[b * 8 + d], s);
                        gate[q] += s;
                    }
                } else {
                    gate[0] += (r == 0 ? xq[0].x : r == 1 ? xq[0].y : r == 2 ? xq[0].z : xq[0].w);
                    gate[1] += (r == 0 ? xq[1].x : r == 1 ? xq[1].y : r == 2 ? xq[1].z : xq[1].w);
                    gate[2] += (r == 0 ? xq[2].x : r == 1 ? xq[2].y : r == 2 ? xq[2].z : xq[2].w);
                    gate[3] += (r == 0 ? xq[3].x : r == 1 ? xq[3].y : r == 2 ? xq[3].z : xq[3].w);
                }
                float cc = sigf(gate[1]) * c[r] + sigf(gate[0]) * tanhf_fast(gate[2]);
                c[r] = cc;
                float h = sigf(gate[3]) * tanhf_fast(cc);
                Hw[b * HID + j] = h;
                if (PHASE == 1)
                    g_h1[((size_t)(blk * S_LEN + t) * BPB + b) * HID + j] = h;
            }
        } else if (PHASE == 1 && tid < 320) {
            int st = tid - 256, b = st >> 3, d = st & 7;
            if (d < DIN) sm[OFF_XS + wb * 64 + b * 8 + d] = xst;
        }
        __syncthreads();   // 2
    }

    if (PHASE == 2 && tid < 256) {
        const float* hfin = sm + OFF_HH;   // t=511 wrote buffer 0
        int w = tid >> 5, lane = tid & 31;
        float s = 0.f;
#pragma unroll
        for (int m = 0; m < HID; m += 32)
            s += hfin[w * HID + lane + m] * __ldg(fcw + lane + m);
#pragma unroll
        for (int o = 16; o > 0; o >>= 1) s += __shfl_down_sync(0xffffffffu, s, o);
        if (lane == 0) out[bg0 + w] = s + __ldg(fcb);
    }
}

// ---------------- launch ----------------
extern "C" void kernel_launch(void* const* d_in, const int* in_sizes, int n_in,
                              void* d_out, int out_size) {
    const float* x    = (const float*)d_in[0];
    const float* wih0 = (const float*)d_in[1];
    const float* whh0 = (const float*)d_in[2];
    const float* bih0 = (const float*)d_in[3];
    const float* bhh0 = (const float*)d_in[4];
    const float* wih1 = (const float*)d_in[5];
    const float* whh1 = (const float*)d_in[6];
    const float* bih1 = (const float*)d_in[7];
    const float* bhh1 = (const float*)d_in[8];
    const float* fcw  = (const float*)d_in[9];
    const float* fcb  = (const float*)d_in[10];
    float* out = (float*)d_out;
    (void)in_sizes; (void)n_in; (void)out_size;

    cudaFuncSetAttribute(lstm_phase<1>, cudaFuncAttributeMaxDynamicSharedMemorySize, PH_SMEM_BYTES);
    cudaFuncSetAttribute(lstm_phase<2>, cudaFuncAttributeMaxDynamicSharedMemorySize, PH_SMEM_BYTES);
    cudaFuncSetAttribute(xg1_gemm,      cudaFuncAttributeMaxDynamicSharedMemorySize, G_SMEM_BYTES);

    pack_kernel<<<(GATES * HID + 255) / 256, 256>>>(whh0, whh1, wih1);
    lstm_phase<1><<<NBLK, NTH, PH_SMEM_BYTES>>>(x, wih0, bih0, bhh0, fcw, fcb, out);
    xg1_gemm<<<dim3(4, NBLK, 2), 256, G_SMEM_BYTES>>>(bih1, bhh1);
    lstm_phase<2><<<NBLK, NTH, PH_SMEM_BYTES>>>(x, wih0, bih1, bhh1, fcw, fcb, out);
}

// round 6
// speedup vs baseline: 1.8838x; 1.8838x over previous
#include <cuda_runtime.h>

// ---------------- problem constants ----------------
#define S_LEN  512
#define DIN    5
#define HID    128
#define GATES  512
#define NBLK   128     // recurrence blocks, each owns BPB batch rows
#define BPB    8
#define NG     32      // k-groups (of 4) per 128-wide K
#define NSM    23      // k-groups cached in smem (rest live in registers)
#define NTH    384     // phase kernel threads = 128 j x 3 kh

// phase smem layout (float offsets)
#define OFF_WC  0
#define OFF_HH  (NSM*GATES*4)             // 47104 : 2 x [8][128] h double buffer
#define OFF_XA  (OFF_HH + 2*BPB*HID)      // 49152 : 2 slots x [8b][4q][128j]
#define OFF_XS  (OFF_XA + 2*4096)         // 57344 : 2 x [8][8] staged x
#define PH_SMEM_BYTES ((OFF_XS + 128)*4)  // 229888

// gemm smem: Ws [32 g][256 c][4k] + Ht 2 x 2048
#define GM_THREADS 512
#define GM_HT_OFF  (NG*256*4)             // 32768 floats
#define GM_SMEM_BYTES ((GM_HT_OFF + 2*2048)*4)   // 147456

// ---------------- global scratch (static) ----------------
__device__ __align__(16) float g_P1[NG * GATES * 4];   // packed w_hh0
__device__ __align__(16) float g_P2[NG * GATES * 4];   // packed w_hh1
__device__ __align__(16) float g_P3[NG * GATES * 4];   // packed w_ih1
__device__ __align__(16) float g_h1 [(size_t)NBLK * S_LEN * BPB * HID];    // [blk][t][b][j]
__device__ __align__(16) float g_xg1[(size_t)NBLK * S_LEN * GATES * BPB];  // [blk][t][col][b]

// ---------------- helpers ----------------
typedef unsigned long long u64;
__device__ __forceinline__ void ffma2(u64 &d, u64 a, u64 b) {
    asm("fma.rn.f32x2 %0, %1, %2, %0;" : "+l"(d) : "l"(a), "l"(b));
}
__device__ __forceinline__ float flo(u64 v) { return __uint_as_float((unsigned)v); }
__device__ __forceinline__ float fhi(u64 v) { return __uint_as_float((unsigned)(v >> 32)); }
__device__ __forceinline__ float sigf(float x) {
    return __fdividef(1.0f, 1.0f + __expf(-x));
}
__device__ __forceinline__ float tanhf_fast(float x) {
    float e = __expf(2.0f * x);
    return 1.0f - __fdividef(2.0f, e + 1.0f);
}

// cached-group accumulation: 4 cols (q*128+j) x 8 b
template<int G0, int G1>
__device__ __forceinline__ void accum_range(u64 (&acc)[4][8],
                                            const ulonglong2* __restrict__ W,
                                            const ulonglong2* __restrict__ H,
                                            int j) {
#pragma unroll 2
    for (int g = G0; g < G1; g++) {
        ulonglong2 w[4];
#pragma unroll
        for (int q = 0; q < 4; q++) w[q] = W[g * GATES + q * HID + j];
#pragma unroll
        for (int b = 0; b < 8; b++) {
            ulonglong2 hv = H[b * 32 + g];
#pragma unroll
            for (int q = 0; q < 4; q++) {
                ffma2(acc[q][b], w[q].x, hv.x);
                ffma2(acc[q][b], w[q].y, hv.y);
            }
        }
    }
}

// ---------------- K1: pack weights ----------------
// P[g][col][dk] = W[col][4g+dk]
__global__ void pack_kernel(const float* __restrict__ whh0,
                            const float* __restrict__ whh1,
                            const float* __restrict__ wih1) {
    int i = blockIdx.x * blockDim.x + threadIdx.x;
    if (i >= GATES * HID) return;
    int col = i / HID, k = i % HID;
    int g = k >> 2, dk = k & 3;
    size_t o = ((size_t)g * GATES + col) * 4 + dk;
    g_P1[o] = whh0[col * HID + k];
    g_P2[o] = whh1[col * HID + k];
    g_P3[o] = wih1[col * HID + k];
}

// ---------------- K3: xg1 = h1 @ w_ih1^T + biases ----------------
// grid (2 col-halves, NBLK, 4 t-quarters), 512 thr, 1 blk/SM.
// thread: cp = tid&255 -> one col; rw = tid>>8 -> one t of the 2-t tile; 8 batch rows.
__global__ void __launch_bounds__(GM_THREADS, 1) xg1_gemm(const float* __restrict__ bih1,
                                                          const float* __restrict__ bhh1) {
    extern __shared__ float sm[];
    float4* Ws4 = (float4*)sm;
    float*  Ht  = sm + GM_HT_OFF;

    const int tid = threadIdx.x;
    const int ch  = blockIdx.x, blk = blockIdx.y, tq = blockIdx.z;
    const int cp  = tid & 255;
    const int rw  = tid >> 8;          // 0/1
    const int col = ch * 256 + cp;
    const int t0  = tq * (S_LEN / 4);  // 128 timesteps per CTA

    // load weight half: 32 g x 256 cols (float4 of 4 k's)
    {
        const float4* P34 = (const float4*)g_P3;
        for (int i = tid; i < NG * 256; i += GM_THREADS) {
            int g = i >> 8, c = i & 255;
            Ws4[i] = __ldg(&P34[g * GATES + ch * 256 + c]);
        }
    }
    const float bias = __ldg(bih1 + col) + __ldg(bhh1 + col);

    // preload tile 0 (2 t's x 8 b x 128 j = 2048 floats)
    {
        const float4* hsrc = (const float4*)(g_h1 + (size_t)(blk * S_LEN + t0) * (BPB * HID));
        ((float4*)Ht)[tid] = __ldg(hsrc + tid);
    }
    __syncthreads();

    const ulonglong2* WsD = (const ulonglong2*)sm;
    int pb = 0;
    for (int tt = 0; tt < S_LEN / 8; tt++) {      // 64 tiles of 2 t's
        const int t = t0 + tt * 2 + rw;
        const bool has = (tt + 1 < S_LEN / 8);
        float4 pre;
        if (has) {
            const float4* hsrc = (const float4*)(g_h1 +
                (size_t)(blk * S_LEN + t0 + (tt + 1) * 2) * (BPB * HID));
            pre = __ldg(hsrc + tid);
        }

        const ulonglong2* HtD = (const ulonglong2*)(Ht + pb * 2048);
        u64 acc[8] = {0ull,0ull,0ull,0ull,0ull,0ull,0ull,0ull};
#pragma unroll 8
        for (int g = 0; g < NG; g++) {
            ulonglong2 w = WsD[g * 256 + cp];
#pragma unroll
            for (int b = 0; b < 8; b++) {
                ulonglong2 hv = HtD[(rw * 8 + b) * 32 + g];
                ffma2(acc[b], w.x, hv.x);
                ffma2(acc[b], w.y, hv.y);
            }
        }
        float o[8];
#pragma unroll
        for (int b = 0; b < 8; b++) o[b] = flo(acc[b]) + fhi(acc[b]) + bias;
        float4* dst = (float4*)(g_xg1 + ((size_t)(blk * S_LEN + t) * GATES + col) * BPB);
        dst[0] = make_float4(o[0], o[1], o[2], o[3]);
        dst[1] = make_float4(o[4], o[5], o[6], o[7]);

        if (has) ((float4*)(Ht + (pb ^ 1) * 2048))[tid] = pre;
        __syncthreads();
        pb ^= 1;
    }
}

// ---------------- K2/K4: recurrent phases (K=128) ----------------
// 384 threads = 128 j x 3 kh. Thread owns all 4 gate-cols of j, 8 batch rows.
// Weights: groups 0-22 in smem; groups 23-31 persistent in registers (3/kh).
// kh0: smem g0-7 + reg g23-25, finalize b0-3. kh1: g8-15 + g26-28, finalize b4-7.
// kh2: g16-22 + g29-31, x staging (phase 1), no finalize.
template<int PHASE>
__global__ void __launch_bounds__(NTH, 1) lstm_phase(
    const float* __restrict__ x,
    const float* __restrict__ wih0,
    const float* __restrict__ bih,
    const float* __restrict__ bhh,
    const float* __restrict__ fcw,
    const float* __restrict__ fcb,
    float* __restrict__ out)
{
    extern __shared__ float sm[];
    const float* Pg = (PHASE == 1) ? g_P1 : g_P2;

    const int tid = threadIdx.x;
    const int j   = tid & (HID - 1);
    const int kh  = tid >> 7;            // 0,1,2
    const int blk = blockIdx.x;
    const int bg0 = blk * BPB;
    const int gb  = NSM + kh * 3;        // first register-resident group

    // persistent register weight groups (3 per thread)
    ulonglong2 wr[3][4];
    {
        const ulonglong2* PgD = (const ulonglong2*)Pg;
#pragma unroll
        for (int s = 0; s < 3; s++)
#pragma unroll
            for (int q = 0; q < 4; q++)
                wr[s][q] = __ldg(&PgD[(gb + s) * GATES + q * HID + j]);
    }

    // finalizer constants
    float bias[4], wihr[4][DIN];
    if (kh < 2) {
#pragma unroll
        for (int q = 0; q < 4; q++) {
            int r = q * HID + j;
            bias[q] = (PHASE == 1) ? (__ldg(bih + r) + __ldg(bhh + r)) : 0.f;
            if (PHASE == 1)
#pragma unroll
                for (int d = 0; d < DIN; d++) wihr[q][d] = __ldg(wih0 + r * DIN + d);
        }
    }

    // load cached weights; zero h buffers; stage x(t=0)
    {
        const float4* src = (const float4*)Pg;
        float4*       dst = (float4*)(sm + OFF_WC);
        for (int i = tid; i < NSM * GATES; i += NTH) dst[i] = __ldg(src + i);
    }
    for (int i = tid; i < 2 * BPB * HID; i += NTH) sm[OFF_HH + i] = 0.f;
    if (PHASE == 1 && tid >= 256 && tid < 320) {
        int st = tid - 256, b = st >> 3, d = st & 7;
        if (d < DIN)
            sm[OFF_XS + b * 8 + d] = __ldg(x + ((size_t)(bg0 + b) * S_LEN + 0) * DIN + d);
    }
    __syncthreads();

    const ulonglong2* WcD = (const ulonglong2*)(sm + OFF_WC);
    float c[4] = {0.f, 0.f, 0.f, 0.f};

    // phase-2: current-step xg (double-buffered across steps)
    float4 xq[4];
    if (PHASE == 2 && kh < 2) {
#pragma unroll
        for (int q = 0; q < 4; q++)
            xq[q] = __ldg((const float4*)(g_xg1 +
                ((size_t)(blk * S_LEN + 0) * GATES + q * HID + j) * BPB + kh * 4));
    }

    for (int t = 0; t < S_LEN; t++) {
        const int rb = t & 1, wb = rb ^ 1;
        const ulonglong2* HrD = (const ulonglong2*)(sm + OFF_HH + rb * BPB * HID);

        // early independent loads for NEXT step
        float4 xqn[4];
        float  xst = 0.f;
        if (PHASE == 2 && kh < 2) {
            int tn = (t + 1 < S_LEN) ? t + 1 : t;
#pragma unroll
            for (int q = 0; q < 4; q++)
                xqn[q] = __ldg((const float4*)(g_xg1 +
                    ((size_t)(blk * S_LEN + tn) * GATES + q * HID + j) * BPB + kh * 4));
        }
        if (PHASE == 1 && kh == 2 && tid < 320) {
            int st = tid - 256, b = st >> 3, d = st & 7;
            int tn = (t + 1 < S_LEN) ? t + 1 : t;
            if (d < DIN) xst = __ldg(x + ((size_t)(bg0 + b) * S_LEN + tn) * DIN + d);
        }

        u64 acc[4][8];
#pragma unroll
        for (int q = 0; q < 4; q++)
#pragma unroll
            for (int b = 0; b < 8; b++) acc[q][b] = 0ull;

        // smem-cached groups
        if (kh == 0)      accum_range<0,  8 >(acc, WcD, HrD, j);
        else if (kh == 1) accum_range<8,  16>(acc, WcD, HrD, j);
        else              accum_range<16, NSM>(acc, WcD, HrD, j);

        // register-resident groups (3)
#pragma unroll
        for (int s = 0; s < 3; s++) {
#pragma unroll
            for (int b = 0; b < 8; b++) {
                ulonglong2 hv = HrD[b * 32 + gb + s];
#pragma unroll
                for (int q = 0; q < 4; q++) {
                    ffma2(acc[q][b], wr[s][q].x, hv.x);
                    ffma2(acc[q][b], wr[s][q].y, hv.y);
                }
            }
        }

        // reduce f32x2 lanes
        float pr[4][8];
#pragma unroll
        for (int q = 0; q < 4; q++)
#pragma unroll
            for (int b = 0; b < 8; b++) pr[q][b] = flo(acc[q][b]) + fhi(acc[q][b]);

        // exports: kh0 -> b4-7 slot0, kh1 -> b0-3 slot0, kh2 -> all b slot1
        if (kh == 0) {
#pragma unroll
            for (int b = 4; b < 8; b++)
#pragma unroll
                for (int q = 0; q < 4; q++)
                    sm[OFF_XA + (b * 4 + q) * HID + j] = pr[q][b];
        } else if (kh == 1) {
#pragma unroll
            for (int b = 0; b < 4; b++)
#pragma unroll
                for (int q = 0; q < 4; q++)
                    sm[OFF_XA + (b * 4 + q) * HID + j] = pr[q][b];
        } else {
#pragma unroll
            for (int b = 0; b < 8; b++)
#pragma unroll
                for (int q = 0; q < 4; q++)
                    sm[OFF_XA + 4096 + (b * 4 + q) * HID + j] = pr[q][b];
        }
        __syncthreads();   // 1

        if (kh < 2) {
            float* Hw = sm + OFF_HH + wb * BPB * HID;
            const float* xs = sm + OFF_XS + rb * 64;
#pragma unroll
            for (int r = 0; r < 4; r++) {
                int b = kh * 4 + r;
                float gate[4];
#pragma unroll
                for (int q = 0; q < 4; q++)
                    gate[q] = pr[q][b]
                            + sm[OFF_XA + (b * 4 + q) * HID + j]
                            + sm[OFF_XA + 4096 + (b * 4 + q) * HID + j];
                if (PHASE == 1) {
#pragma unroll
                    for (int q = 0; q < 4; q++) {
                        float s = bias[q];
#pragma unroll
                        for (int d = 0; d < DIN; d++) s = fmaf(wihr[q][d], xs[b * 8 + d], s);
                        gate[q] += s;
                    }
                } else {
#pragma unroll
                    for (int q = 0; q < 4; q++)
                        gate[q] += ((const float*)&xq[q])[r];
                }
                float cc = sigf(gate[1]) * c[r] + sigf(gate[0]) * tanhf_fast(gate[2]);
                c[r] = cc;
                float h = sigf(gate[3]) * tanhf_fast(cc);
                Hw[b * HID + j] = h;
                if (PHASE == 1)
                    g_h1[((size_t)(blk * S_LEN + t) * BPB + b) * HID + j] = h;
            }
        } else if (PHASE == 1 && tid < 320) {
            int st = tid - 256, b = st >> 3, d = st & 7;
            if (d < DIN) sm[OFF_XS + wb * 64 + b * 8 + d] = xst;
        }
        __syncthreads();   // 2

        if (PHASE == 2 && kh < 2) {
#pragma unroll
            for (int q = 0; q < 4; q++) xq[q] = xqn[q];
        }
    }

    if (PHASE == 2 && tid < 256) {
        const float* hfin = sm + OFF_HH;   // t=511 wrote buffer 0
        int w = tid >> 5, lane = tid & 31;
        float s = 0.f;
#pragma unroll
        for (int m = 0; m < HID; m += 32)
            s += hfin[w * HID + lane + m] * __ldg(fcw + lane + m);
#pragma unroll
        for (int o = 16; o > 0; o >>= 1) s += __shfl_down_sync(0xffffffffu, s, o);
        if (lane == 0) out[bg0 + w] = s + __ldg(fcb);
    }
}

// ---------------- launch ----------------
extern "C" void kernel_launch(void* const* d_in, const int* in_sizes, int n_in,
                              void* d_out, int out_size) {
    const float* x    = (const float*)d_in[0];
    const float* wih0 = (const float*)d_in[1];
    const float* whh0 = (const float*)d_in[2];
    const float* bih0 = (const float*)d_in[3];
    const float* bhh0 = (const float*)d_in[4];
    const float* wih1 = (const float*)d_in[5];
    const float* whh1 = (const float*)d_in[6];
    const float* bih1 = (const float*)d_in[7];
    const float* bhh1 = (const float*)d_in[8];
    const float* fcw  = (const float*)d_in[9];
    const float* fcb  = (const float*)d_in[10];
    float* out = (float*)d_out;
    (void)in_sizes; (void)n_in; (void)out_size;

    cudaFuncSetAttribute(lstm_phase<1>, cudaFuncAttributeMaxDynamicSharedMemorySize, PH_SMEM_BYTES);
    cudaFuncSetAttribute(lstm_phase<2>, cudaFuncAttributeMaxDynamicSharedMemorySize, PH_SMEM_BYTES);
    cudaFuncSetAttribute(xg1_gemm,      cudaFuncAttributeMaxDynamicSharedMemorySize, GM_SMEM_BYTES);

    pack_kernel<<<(GATES * HID + 255) / 256, 256>>>(whh0, whh1, wih1);
    lstm_phase<1><<<NBLK, NTH, PH_SMEM_BYTES>>>(x, wih0, bih0, bhh0, fcw, fcb, out);
    xg1_gemm<<<dim3(2, NBLK, 4), GM_THREADS, GM_SMEM_BYTES>>>(bih1, bhh1);
    lstm_phase<2><<<NBLK, NTH, PH_SMEM_BYTES>>>(x, wih0, bih1, bhh1, fcw, fcb, out);
}

// round 7
// speedup vs baseline: 2.1274x; 1.1293x over previous
#include <cuda_runtime.h>

// ---------------- problem constants ----------------
#define S_LEN  512
#define DIN    5
#define HID    128
#define GATES  512
#define NBLK   128     // recurrence blocks, each owns BPB batch rows
#define BPB    8
#define NG     32      // k-groups (of 4) per 128-wide K
#define NSM    23      // k-groups cached in smem (rest in registers)
#define NTH    384     // phase threads = 128 j x 3 kh

// phase smem layout (float offsets)
#define OFF_WC  0
#define OFF_HA  (NSM*GATES*4)            // 47104 : hA [4b][128j]
#define OFF_HB  (OFF_HA + 512)           // 47616 : hB
#define OFF_XP  (OFF_HB + 512)           // 48128 : partials [2 half][2 slot][4 b][4 q][128 j]
#define PH_SMEM_BYTES ((OFF_XP + 8192)*4)   // 225280

// gemm smem: Ws [32 g][256 c][4k] + Ht 2 x 4096
#define GM_THREADS 512
#define GM_HT_OFF  (NG*256*4)            // 32768 floats
#define GM_SMEM_BYTES ((GM_HT_OFF + 2*4096)*4)   // 163840

// ---------------- global scratch (static) ----------------
__device__ __align__(16) float g_P1[NG * GATES * 4];   // packed w_hh0
__device__ __align__(16) float g_P2[NG * GATES * 4];   // packed w_hh1
__device__ __align__(16) float g_P3[NG * GATES * 4];   // packed w_ih1
__device__ __align__(16) float g_h1 [(size_t)NBLK * S_LEN * BPB * HID];    // [blk][t][b][j]
__device__ __align__(16) float g_xg1[(size_t)NBLK * S_LEN * GATES * BPB];  // [blk][t][col][b]

// ---------------- helpers ----------------
typedef unsigned long long u64;
__device__ __forceinline__ void ffma2(u64 &d, u64 a, u64 b) {
    asm("fma.rn.f32x2 %0, %1, %2, %0;" : "+l"(d) : "l"(a), "l"(b));
}
__device__ __forceinline__ float flo(u64 v) { return __uint_as_float((unsigned)v); }
__device__ __forceinline__ float fhi(u64 v) { return __uint_as_float((unsigned)(v >> 32)); }
__device__ __forceinline__ float sigf(float x) {
    return __fdividef(1.0f, 1.0f + __expf(-x));
}
__device__ __forceinline__ float tanhf_fast(float x) {
    float e = __expf(2.0f * x);
    return 1.0f - __fdividef(2.0f, e + 1.0f);
}

// smem-group accumulation over 4 batch rows
template<int G0, int G1>
__device__ __forceinline__ void accum_smem(u64 (&acc)[4][4],
                                           const ulonglong2* __restrict__ W,
                                           const ulonglong2* __restrict__ H,
                                           int j) {
#pragma unroll
    for (int g = G0; g < G1; g++) {
        ulonglong2 w[4];
#pragma unroll
        for (int q = 0; q < 4; q++) w[q] = W[g * GATES + q * HID + j];
#pragma unroll
        for (int b = 0; b < 4; b++) {
            ulonglong2 hv = H[b * 32 + g];
#pragma unroll
            for (int q = 0; q < 4; q++) {
                ffma2(acc[q][b], w[q].x, hv.x);
                ffma2(acc[q][b], w[q].y, hv.y);
            }
        }
    }
}

// ---------------- K1: pack weights ----------------
__global__ void pack_kernel(const float* __restrict__ whh0,
                            const float* __restrict__ whh1,
                            const float* __restrict__ wih1) {
    int i = blockIdx.x * blockDim.x + threadIdx.x;
    if (i >= GATES * HID) return;
    int col = i / HID, k = i % HID;
    int g = k >> 2, dk = k & 3;
    size_t o = ((size_t)g * GATES + col) * 4 + dk;
    g_P1[o] = whh0[col * HID + k];
    g_P2[o] = whh1[col * HID + k];
    g_P3[o] = wih1[col * HID + k];
}

// ---------------- K3: xg1 = h1 @ w_ih1^T + biases ----------------
// grid (2 ch, NBLK, 4 tq), 512 thr. thread: cp=tid&127 -> 2 cols, rw=tid>>7 -> 1 t of 4-t tile, 8 b.
__global__ void __launch_bounds__(GM_THREADS, 1) xg1_gemm(const float* __restrict__ bih1,
                                                          const float* __restrict__ bhh1) {
    extern __shared__ float sm[];
    float4* Ws4 = (float4*)sm;
    float*  Ht  = sm + GM_HT_OFF;

    const int tid = threadIdx.x;
    const int ch  = blockIdx.x, blk = blockIdx.y, tq = blockIdx.z;
    const int cp  = tid & 127;
    const int rw  = tid >> 7;                 // 0..3
    const int c0  = ch * 256 + cp * 2;
    const int t0  = tq * (S_LEN / 4);         // 128 t per CTA

    // weight half: 32 g x 256 cols
    {
        const float4* P34 = (const float4*)g_P3;
        for (int i = tid; i < NG * 256; i += GM_THREADS) {
            int g = i >> 8, c = i & 255;
            Ws4[i] = __ldg(&P34[g * GATES + ch * 256 + c]);
        }
    }
    const float bs0 = __ldg(bih1 + c0)     + __ldg(bhh1 + c0);
    const float bs1 = __ldg(bih1 + c0 + 1) + __ldg(bhh1 + c0 + 1);

    // preload tile 0 (4 t x 8 b x 128 j = 4096 floats)
    {
        const float4* hsrc = (const float4*)(g_h1 + (size_t)(blk * S_LEN + t0) * (BPB * HID));
        ((float4*)Ht)[tid * 2]     = __ldg(hsrc + tid * 2);
        ((float4*)Ht)[tid * 2 + 1] = __ldg(hsrc + tid * 2 + 1);
    }
    __syncthreads();

    const ulonglong2* WsD = (const ulonglong2*)sm;
    int pb = 0;
    for (int tt = 0; tt < 32; tt++) {
        const int t = t0 + tt * 4 + rw;
        const bool has = (tt + 1 < 32);
        float4 pre0, pre1;
        if (has) {
            const float4* hsrc = (const float4*)(g_h1 +
                (size_t)(blk * S_LEN + t0 + (tt + 1) * 4) * (BPB * HID));
            pre0 = __ldg(hsrc + tid * 2);
            pre1 = __ldg(hsrc + tid * 2 + 1);
        }

        const ulonglong2* HtD = (const ulonglong2*)(Ht + pb * 4096);
        u64 a0[8] = {0,0,0,0,0,0,0,0}, a1[8] = {0,0,0,0,0,0,0,0};
#pragma unroll 8
        for (int g = 0; g < NG; g++) {
            ulonglong2 w0 = WsD[g * 256 + cp * 2];
            ulonglong2 w1 = WsD[g * 256 + cp * 2 + 1];
#pragma unroll
            for (int b = 0; b < 8; b++) {
                ulonglong2 hv = HtD[(rw * 8 + b) * 32 + g];
                ffma2(a0[b], w0.x, hv.x); ffma2(a0[b], w0.y, hv.y);
                ffma2(a1[b], w1.x, hv.x); ffma2(a1[b], w1.y, hv.y);
            }
        }
        float o0[8], o1[8];
#pragma unroll
        for (int b = 0; b < 8; b++) {
            o0[b] = flo(a0[b]) + fhi(a0[b]) + bs0;
            o1[b] = flo(a1[b]) + fhi(a1[b]) + bs1;
        }
        float4* dst = (float4*)(g_xg1 + ((size_t)(blk * S_LEN + t) * GATES + c0) * BPB);
        dst[0] = make_float4(o0[0], o0[1], o0[2], o0[3]);
        dst[1] = make_float4(o0[4], o0[5], o0[6], o0[7]);
        dst[2] = make_float4(o1[0], o1[1], o1[2], o1[3]);
        dst[3] = make_float4(o1[4], o1[5], o1[6], o1[7]);

        if (has) {
            ((float4*)(Ht + (pb ^ 1) * 4096))[tid * 2]     = pre0;
            ((float4*)(Ht + (pb ^ 1) * 4096))[tid * 2 + 1] = pre1;
        }
        __syncthreads();
        pb ^= 1;
    }
}

// ---------------- K2/K4: recurrent phases, batch-half pipelined ----------------
// 384 thr = 128 j x 3 kh. Half A = batch rows 0-3, half B = rows 4-7.
// Phase alpha: GEMM_A(t) + finalize_B(t-1). Phase beta: GEMM_B(t) + finalize_A(t).
// kh0: smem g0-6 + reg g23-25, finalizes local rows 0,1 (exports 2,3 -> slot0)
// kh1: smem g7-13 + reg g26-28, finalizes rows 2,3 (exports 0,1 -> slot0)
// kh2: smem g14-22 + reg g29-31, exports all rows -> slot1
template<int PHASE>
__global__ void __launch_bounds__(NTH, 1) lstm_phase(
    const float* __restrict__ x,
    const float* __restrict__ wih0,
    const float* __restrict__ bih,
    const float* __restrict__ bhh,
    const float* __restrict__ fcw,
    const float* __restrict__ fcb,
    float* __restrict__ out)
{
    extern __shared__ float sm[];
    const float* Pg = (PHASE == 1) ? g_P1 : g_P2;

    const int tid = threadIdx.x;
    const int j   = tid & (HID - 1);
    const int kh  = tid >> 7;
    const int blk = blockIdx.x;
    const int bg0 = blk * BPB;
    const int gb  = NSM + kh * 3;

    // register-resident weight groups
    ulonglong2 wr[3][4];
    {
        const ulonglong2* PgD = (const ulonglong2*)Pg;
#pragma unroll
        for (int s = 0; s < 3; s++)
#pragma unroll
            for (int q = 0; q < 4; q++)
                wr[s][q] = __ldg(&PgD[(gb + s) * GATES + q * HID + j]);
    }

    // finalizer constants (phase1 only; phase2 biases live in xg1)
    float bias[4], wihr[4][DIN];
    if (PHASE == 1 && kh < 2) {
#pragma unroll
        for (int q = 0; q < 4; q++) {
            int r = q * HID + j;
            bias[q] = __ldg(bih + r) + __ldg(bhh + r);
#pragma unroll
            for (int d = 0; d < DIN; d++) wihr[q][d] = __ldg(wih0 + r * DIN + d);
        }
    }

    // load smem weights; zero h buffers
    {
        const float4* src = (const float4*)Pg;
        float4*       dst = (float4*)(sm + OFF_WC);
        for (int i = tid; i < NSM * GATES; i += NTH) dst[i] = __ldg(src + i);
    }
    for (int i = tid; i < 1024; i += NTH) sm[OFF_HA + i] = 0.f;
    __syncthreads();

    const ulonglong2* WcD = (const ulonglong2*)(sm + OFF_WC);

    float c[2][2] = {{0.f, 0.f}, {0.f, 0.f}};       // [half][row]
    float prB[4][2];                                 // own B partials held across barrier
    float2 xqA[4], xqB[4];                           // phase2 inputs
    float  xvA[2][DIN], xvB[2][DIN];                 // phase1 inputs

    // gemm over one half + export + own-save
    auto gemm_half = [&](int hoff, int half, float (&prOwn)[4][2]) {
        const ulonglong2* H = (const ulonglong2*)(sm + hoff);
        u64 acc[4][4];
#pragma unroll
        for (int q = 0; q < 4; q++)
#pragma unroll
            for (int b = 0; b < 4; b++) acc[q][b] = 0ull;
        if (kh == 0)      accum_smem<0,  7 >(acc, WcD, H, j);
        else if (kh == 1) accum_smem<7,  14>(acc, WcD, H, j);
        else              accum_smem<14, NSM>(acc, WcD, H, j);
#pragma unroll
        for (int s = 0; s < 3; s++) {
#pragma unroll
            for (int b = 0; b < 4; b++) {
                ulonglong2 hv = H[b * 32 + gb + s];
#pragma unroll
                for (int q = 0; q < 4; q++) {
                    ffma2(acc[q][b], wr[s][q].x, hv.x);
                    ffma2(acc[q][b], wr[s][q].y, hv.y);
                }
            }
        }
        float pr[4][4];
#pragma unroll
        for (int q = 0; q < 4; q++)
#pragma unroll
            for (int b = 0; b < 4; b++) pr[q][b] = flo(acc[q][b]) + fhi(acc[q][b]);

        float* XP = sm + OFF_XP + half * 4096;
        if (kh == 0) {
#pragma unroll
            for (int r = 2; r < 4; r++)
#pragma unroll
                for (int q = 0; q < 4; q++) XP[(r * 4 + q) * HID + j] = pr[q][r];
#pragma unroll
            for (int q = 0; q < 4; q++) { prOwn[q][0] = pr[q][0]; prOwn[q][1] = pr[q][1]; }
        } else if (kh == 1) {
#pragma unroll
            for (int r = 0; r < 2; r++)
#pragma unroll
                for (int q = 0; q < 4; q++) XP[(r * 4 + q) * HID + j] = pr[q][r];
#pragma unroll
            for (int q = 0; q < 4; q++) { prOwn[q][0] = pr[q][2]; prOwn[q][1] = pr[q][3]; }
        } else {
#pragma unroll
            for (int r = 0; r < 4; r++)
#pragma unroll
                for (int q = 0; q < 4; q++) XP[2048 + (r * 4 + q) * HID + j] = pr[q][r];
        }
    };

    // finalize 2 rows of a half (kh<2 only)
    auto finalize_half = [&](int hoff, int half, int t, float (&prOwn)[4][2],
                             float2 (&xq)[4], float (&xv)[2][DIN]) {
        const float* XP = sm + OFF_XP + half * 4096;
#pragma unroll
        for (int r2 = 0; r2 < 2; r2++) {
            int rloc = 2 * kh + r2;
            float gate[4];
#pragma unroll
            for (int q = 0; q < 4; q++)
                gate[q] = prOwn[q][r2]
                        + XP[(rloc * 4 + q) * HID + j]
                        + XP[2048 + (rloc * 4 + q) * HID + j];
            if (PHASE == 1) {
#pragma unroll
                for (int q = 0; q < 4; q++) {
                    float s = bias[q];
#pragma unroll
                    for (int d = 0; d < DIN; d++) s = fmaf(wihr[q][d], xv[r2][d], s);
                    gate[q] += s;
                }
            } else {
                gate[0] += (r2 == 0 ? xq[0].x : xq[0].y);
                gate[1] += (r2 == 0 ? xq[1].x : xq[1].y);
                gate[2] += (r2 == 0 ? xq[2].x : xq[2].y);
                gate[3] += (r2 == 0 ? xq[3].x : xq[3].y);
            }
            float cc = sigf(gate[1]) * c[half][r2] + sigf(gate[0]) * tanhf_fast(gate[2]);
            c[half][r2] = cc;
            float h = sigf(gate[3]) * tanhf_fast(cc);
            sm[hoff + rloc * HID + j] = h;
            if (PHASE == 1)
                g_h1[((size_t)(blk * S_LEN + t) * BPB + half * 4 + rloc) * HID + j] = h;
        }
    };

    auto load_inputs = [&](int half, int t, float2 (&xq)[4], float (&xv)[2][DIN]) {
        if (kh >= 2) return;
        if (PHASE == 2) {
            const float* xp = g_xg1 + (size_t)(blk * S_LEN + t) * (GATES * BPB);
#pragma unroll
            for (int q = 0; q < 4; q++)
                xq[q] = __ldg((const float2*)(xp + (q * HID + j) * BPB + half * 4 + 2 * kh));
        } else {
#pragma unroll
            for (int r2 = 0; r2 < 2; r2++) {
                int b = half * 4 + 2 * kh + r2;
                const float* xr = x + ((size_t)(bg0 + b) * S_LEN + t) * DIN;
#pragma unroll
                for (int d = 0; d < DIN; d++) xv[r2][d] = __ldg(xr + d);
            }
        }
    };

    for (int t = 0; t < S_LEN; t++) {
        // ---- phase alpha: GEMM_A(t) + finalize_B(t-1) ----
        load_inputs(0, t, xqA, xvA);          // for finalize_A(t) in beta
        if (t > 0 && kh < 2) finalize_half(OFF_HB, 1, t - 1, prB, xqB, xvB);
        {
            float prA[4][2];
            gemm_half(OFF_HA, 0, prA);
            __syncthreads();
            // ---- phase beta: GEMM_B(t) + finalize_A(t) ----
            load_inputs(1, t, xqB, xvB);      // for finalize_B(t) in next alpha
            if (kh < 2) finalize_half(OFF_HA, 0, t, prA, xqA, xvA);
        }
        gemm_half(OFF_HB, 1, prB);
        __syncthreads();
    }
    // drain: finalize_B(511)
    if (kh < 2) finalize_half(OFF_HB, 1, S_LEN - 1, prB, xqB, xvB);
    __syncthreads();

    if (PHASE == 2 && tid < 256) {
        int w = tid >> 5, lane = tid & 31;
        const float* hrow = sm + (w < 4 ? OFF_HA + w * HID : OFF_HB + (w - 4) * HID);
        float s = 0.f;
#pragma unroll
        for (int m = 0; m < HID; m += 32)
            s += hrow[lane + m] * __ldg(fcw + lane + m);
#pragma unroll
        for (int o = 16; o > 0; o >>= 1) s += __shfl_down_sync(0xffffffffu, s, o);
        if (lane == 0) out[bg0 + w] = s + __ldg(fcb);
    }
}

// ---------------- launch ----------------
extern "C" void kernel_launch(void* const* d_in, const int* in_sizes, int n_in,
                              void* d_out, int out_size) {
    const float* x    = (const float*)d_in[0];
    const float* wih0 = (const float*)d_in[1];
    const float* whh0 = (const float*)d_in[2];
    const float* bih0 = (const float*)d_in[3];
    const float* bhh0 = (const float*)d_in[4];
    const float* wih1 = (const float*)d_in[5];
    const float* whh1 = (const float*)d_in[6];
    const float* bih1 = (const float*)d_in[7];
    const float* bhh1 = (const float*)d_in[8];
    const float* fcw  = (const float*)d_in[9];
    const float* fcb  = (const float*)d_in[10];
    float* out = (float*)d_out;
    (void)in_sizes; (void)n_in; (void)out_size;

    cudaFuncSetAttribute(lstm_phase<1>, cudaFuncAttributeMaxDynamicSharedMemorySize, PH_SMEM_BYTES);
    cudaFuncSetAttribute(lstm_phase<2>, cudaFuncAttributeMaxDynamicSharedMemorySize, PH_SMEM_BYTES);
    cudaFuncSetAttribute(xg1_gemm,      cudaFuncAttributeMaxDynamicSharedMemorySize, GM_SMEM_BYTES);

    pack_kernel<<<(GATES * HID + 255) / 256, 256>>>(whh0, whh1, wih1);
    lstm_phase<1><<<NBLK, NTH, PH_SMEM_BYTES>>>(x, wih0, bih0, bhh0, fcw, fcb, out);
    xg1_gemm<<<dim3(2, NBLK, 4), GM_THREADS, GM_SMEM_BYTES>>>(bih1, bhh1);
    lstm_phase<2><<<NBLK, NTH, PH_SMEM_BYTES>>>(x, wih0, bih1, bhh1, fcw, fcb, out);
}